// round 1
// baseline (speedup 1.0000x reference)
#include <cuda_runtime.h>
#include <cstdint>

#define Bsz 8
#define Nn 1024
#define Hh 8
#define FOv 64
#define FINv 256

// ---------------- device scratch (no allocations allowed) ----------------
__device__ unsigned g_abits[Bsz * Nn * 32];                 // 1 MB  packed adjacency
__device__ float g_h[(size_t)Bsz * Hh * Nn * FOv];          // 16 MB h[b][h][n][o]
__device__ float g_s[Bsz * Hh * Nn];                        // src attn term
__device__ float g_d[Bsz * Hh * Nn];                        // dst attn term
__device__ float g_hout[(size_t)Bsz * Hh * Nn * FOv];       // 16 MB per-head softmax-agg output

// ---------------- K0: pack adjacency rows into bitmasks ----------------
__global__ void k_pack(const int* __restrict__ A) {
    int warp = (blockIdx.x * blockDim.x + threadIdx.x) >> 5;   // one warp per row, 8192 rows
    int lane = threadIdx.x & 31;
    const int* row = A + (size_t)warp * Nn;
    unsigned* dst = g_abits + warp * 32;
    #pragma unroll
    for (int w = 0; w < 32; w++) {
        unsigned bits = __ballot_sync(0xffffffffu, row[w * 32 + lane] > 0);
        if (lane == 0) dst[w] = bits;
    }
}

// ---------------- K1: h[b,h,n,o] = sum_f (x*Npost*e)[b,n,f] * w[h,f,o] ----------------
// Tile: 64 n x 64 o (one head) per CTA, K-chunks of 16, 128 threads, 8x4 per-thread tile.
__global__ __launch_bounds__(128) void k_feat(
    const float* __restrict__ x, const float* __restrict__ e,
    const float* __restrict__ Np, const float* __restrict__ w)
{
    __shared__ float aT[16][68];   // recx^T  [k][n]
    __shared__ float bs[16][68];   // w tile  [k][o]
    int nt = blockIdx.x, h = blockIdx.y, b = blockIdx.z;
    int n0 = nt * 64;
    int tid = threadIdx.x;
    int tn = tid >> 4, to = tid & 15;           // compute mapping: n=tn*8+i, o=to*4+j
    const float* wg = w + (size_t)h * FINv * FOv;
    float acc[8][4];
    #pragma unroll
    for (int i = 0; i < 8; i++)
        #pragma unroll
        for (int j = 0; j < 4; j++) acc[i][j] = 0.f;

    int kk  = tid & 15, nb  = tid >> 4;         // recx loader coords
    int oo  = tid & 63, kk2 = tid >> 6;         // w loader coords

    for (int kc = 0; kc < FINv; kc += 16) {
        __syncthreads();
        {
            int f = kc + kk;
            float xv = x[b * FINv + f];
            const float* Npf = Np + f;
            const float* ef  = e + (size_t)b * Nn * FINv + f;
            #pragma unroll
            for (int i = 0; i < 8; i++) {
                int n = nb + i * 8;
                int ng = n0 + n;
                aT[kk][n] = xv * Npf[ng * FINv] * ef[(size_t)ng * FINv];
            }
            #pragma unroll
            for (int i = 0; i < 8; i++) {
                int k = kk2 + i * 2;
                bs[k][oo] = wg[(kc + k) * FOv + oo];
            }
        }
        __syncthreads();
        #pragma unroll
        for (int k = 0; k < 16; k++) {
            float4 a0 = *(float4*)&aT[k][tn * 8];
            float4 a1 = *(float4*)&aT[k][tn * 8 + 4];
            float4 bv = *(float4*)&bs[k][to * 4];
            float av[8] = {a0.x, a0.y, a0.z, a0.w, a1.x, a1.y, a1.z, a1.w};
            float bw[4] = {bv.x, bv.y, bv.z, bv.w};
            #pragma unroll
            for (int i = 0; i < 8; i++)
                #pragma unroll
                for (int j = 0; j < 4; j++)
                    acc[i][j] += av[i] * bw[j];
        }
    }
    float* dst = g_h + (((size_t)(b * Hh + h)) * Nn + n0) * FOv;
    #pragma unroll
    for (int i = 0; i < 8; i++) {
        int n = tn * 8 + i;
        float4 v = make_float4(acc[i][0], acc[i][1], acc[i][2], acc[i][3]);
        *(float4*)&dst[(size_t)n * FOv + to * 4] = v;
    }
}

// ---------------- K2: s,d attention terms (warp per (b,h,n)) ----------------
__global__ void k_sd(const float* __restrict__ a_src, const float* __restrict__ a_dst) {
    int gw = (blockIdx.x * blockDim.x + threadIdx.x) >> 5;   // (b*H+h)*N + n
    int lane = threadIdx.x & 31;
    int h = (gw >> 10) & 7;
    const float* hp = g_h + (size_t)gw * FOv;
    float v0 = hp[lane], v1 = hp[lane + 32];
    float s = v0 * a_src[h * FOv + lane] + v1 * a_src[h * FOv + lane + 32];
    float d = v0 * a_dst[h * FOv + lane] + v1 * a_dst[h * FOv + lane + 32];
    #pragma unroll
    for (int off = 16; off; off >>= 1) {
        s += __shfl_down_sync(0xffffffffu, s, off);
        d += __shfl_down_sync(0xffffffffu, d, off);
    }
    if (lane == 0) { g_s[gw] = s; g_d[gw] = d; }
}

// ---------------- K3: fused masked softmax + aggregation ----------------
// CTA per (b, h, 128-row tile). Stream m in chunks of 32 (one bitmask word/row).
// Phase1: W[m][n] = adj ? exp(leaky(s_n + d_m)) : 0  (rowsum in registers).
// Phase2: acc[128x64] += W^T x h  using packed fma.rn.f32x2 (FFMA2, 2x fp32 rate).
__global__ __launch_bounds__(128) void k_attn() {
    __shared__ float hs[32][68];     // h chunk   [m][o]
    __shared__ float Wt[32][132];    // weights   [m][n]
    __shared__ float rs_sm[128];     // rowsums
    int nt = blockIdx.x, h = blockIdx.y, b = blockIdx.z;
    int n0 = nt * 128;
    int tid = threadIdx.x;
    int bh = b * Hh + h;
    const float* hbase = g_h + (size_t)bh * Nn * FOv;
    const float* dbase = g_d + bh * Nn;
    float s_n = g_s[bh * Nn + n0 + tid];
    const unsigned* bitrow = g_abits + (size_t)(b * Nn + n0 + tid) * 32;
    float rs = 0.f;
    int tn = tid >> 3, to = tid & 7;           // n = tn*8+i, o = to*8 + 2j(+1)
    unsigned long long acc[8][4];              // packed f32x2 accumulators
    #pragma unroll
    for (int i = 0; i < 8; i++)
        #pragma unroll
        for (int j = 0; j < 4; j++) acc[i][j] = 0ull;

    for (int c = 0; c < 32; c++) {
        int m0 = c * 32;
        __syncthreads();
        // load h chunk (coalesced float4)
        #pragma unroll
        for (int i = 0; i < 4; i++) {
            int f4 = i * 128 + tid;
            int m = f4 >> 4, o4 = f4 & 15;
            *(float4*)&hs[m][o4 * 4] = *(const float4*)&hbase[(size_t)(m0 + m) * FOv + o4 * 4];
        }
        // phase 1: this thread owns row n0+tid
        unsigned bits = bitrow[c];
        #pragma unroll
        for (int m = 0; m < 32; m++) {
            float t = s_n + __ldg(&dbase[m0 + m]);
            float l = fmaxf(t, 0.2f * t);                       // leaky_relu
            float wv = ((bits >> m) & 1u) ? __expf(l) : 0.f;    // masked exp
            rs += wv;
            Wt[m][tid] = wv;
        }
        __syncthreads();
        // phase 2: W x h with packed-f32x2 FMA
        #pragma unroll 2
        for (int m = 0; m < 32; m++) {
            ulonglong2 hA = *(ulonglong2*)&hs[m][to * 8];        // pairs (o,o+1),(o+2,o+3)
            ulonglong2 hB = *(ulonglong2*)&hs[m][to * 8 + 4];
            unsigned long long hv[4] = {hA.x, hA.y, hB.x, hB.y};
            #pragma unroll
            for (int i = 0; i < 8; i++) {
                float wv = Wt[m][tn * 8 + i];
                unsigned long long wp;
                asm("mov.b64 %0, {%1, %1};" : "=l"(wp) : "f"(wv));
                #pragma unroll
                for (int j = 0; j < 4; j++)
                    asm("fma.rn.f32x2 %0, %1, %2, %0;"
                        : "+l"(acc[i][j]) : "l"(wp), "l"(hv[j]));
            }
        }
    }
    rs_sm[tid] = rs;
    __syncthreads();
    float* obase = g_hout + ((size_t)bh * Nn + n0) * FOv;
    #pragma unroll
    for (int i = 0; i < 8; i++) {
        int n = tn * 8 + i;
        float inv = 1.f / rs_sm[n];
        float2 p0 = *(float2*)&acc[i][0];
        float2 p1 = *(float2*)&acc[i][1];
        float2 p2 = *(float2*)&acc[i][2];
        float2 p3 = *(float2*)&acc[i][3];
        float4 o0 = make_float4(p0.x * inv, p0.y * inv, p1.x * inv, p1.y * inv);
        float4 o1 = make_float4(p2.x * inv, p2.y * inv, p3.x * inv, p3.y * inv);
        *(float4*)&obase[(size_t)n * FOv + to * 8]     = o0;
        *(float4*)&obase[(size_t)n * FOv + to * 8 + 4] = o1;
    }
}

// ---------------- K4: head mean + bias + node mask ----------------
__global__ void k_final(const float* __restrict__ mask, const float* __restrict__ bias,
                        float* __restrict__ out) {
    int idx = blockIdx.x * blockDim.x + threadIdx.x;   // float4 index, total 131072
    int o4 = idx & 15;
    int n  = (idx >> 4) & (Nn - 1);
    int b  = idx >> 14;
    float4 acc = make_float4(0.f, 0.f, 0.f, 0.f);
    #pragma unroll
    for (int h = 0; h < Hh; h++) {
        const float4 v = *(const float4*)&g_hout[(((size_t)(b * Hh + h)) * Nn + n) * FOv + o4 * 4];
        acc.x += v.x; acc.y += v.y; acc.z += v.z; acc.w += v.w;
    }
    float mz = mask[b * Nn + n];
    float m8 = mz * 0.125f;
    float4 bv = *(const float4*)&bias[o4 * 4];
    float4 r;
    r.x = fmaf(acc.x, m8, mz * bv.x);
    r.y = fmaf(acc.y, m8, mz * bv.y);
    r.z = fmaf(acc.z, m8, mz * bv.z);
    r.w = fmaf(acc.w, m8, mz * bv.w);
    ((float4*)out)[idx] = r;
}

// ---------------- launch ----------------
extern "C" void kernel_launch(void* const* d_in, const int* in_sizes, int n_in,
                              void* d_out, int out_size) {
    const float* x     = (const float*)d_in[0];
    const int*   A     = (const int*)  d_in[1];
    const float* mask  = (const float*)d_in[2];
    // d_in[3] = p_atten (unused in forward)
    const float* e     = (const float*)d_in[4];
    const float* Np    = (const float*)d_in[5];
    const float* w     = (const float*)d_in[6];
    const float* a_src = (const float*)d_in[7];
    const float* a_dst = (const float*)d_in[8];
    const float* bias  = (const float*)d_in[9];
    float* out = (float*)d_out;

    k_pack <<<1024, 256>>>(A);                       // 8192 rows, 1 warp each
    k_feat <<<dim3(16, Hh, Bsz), 128>>>(x, e, Np, w);
    k_sd   <<<8192, 256>>>(a_src, a_dst);            // 65536 warps
    k_attn <<<dim3(8, Hh, Bsz), 128>>>();
    k_final<<<512, 256>>>(mask, bias, out);
}

// round 3
// speedup vs baseline: 1.7770x; 1.7770x over previous
#include <cuda_runtime.h>
#include <cstdint>

#define Bsz 8
#define Nn 1024
#define Hh 8
#define FOv 64
#define FINv 256

// ---------------- device scratch ----------------
__device__ unsigned g_abits[Bsz * Nn * 32];                 // packed adjacency
__device__ float g_h[(size_t)Bsz * Hh * Nn * FOv];          // h[b][h][n][o]
__device__ float g_s[Bsz * Hh * Nn];
__device__ float g_d[Bsz * Hh * Nn];
__device__ float g_hout[(size_t)Bsz * Hh * Nn * FOv];

// ---------------- K0: pack adjacency ----------------
__global__ void k_pack(const int* __restrict__ A) {
    int warp = (blockIdx.x * blockDim.x + threadIdx.x) >> 5;
    int lane = threadIdx.x & 31;
    const int* row = A + (size_t)warp * Nn;
    unsigned* dst = g_abits + warp * 32;
    #pragma unroll
    for (int w = 0; w < 32; w++) {
        unsigned bits = __ballot_sync(0xffffffffu, row[w * 32 + lane] > 0);
        if (lane == 0) dst[w] = bits;
    }
}

// ---------------- K1: feature GEMM (fp32 SIMT) ----------------
__global__ __launch_bounds__(128) void k_feat(
    const float* __restrict__ x, const float* __restrict__ e,
    const float* __restrict__ Np, const float* __restrict__ w)
{
    __shared__ float aT[16][68];
    __shared__ float bs[16][68];
    int nt = blockIdx.x, h = blockIdx.y, b = blockIdx.z;
    int n0 = nt * 64;
    int tid = threadIdx.x;
    int tn = tid >> 4, to = tid & 15;
    const float* wg = w + (size_t)h * FINv * FOv;
    float acc[8][4];
    #pragma unroll
    for (int i = 0; i < 8; i++)
        #pragma unroll
        for (int j = 0; j < 4; j++) acc[i][j] = 0.f;

    int kk = tid & 15, nb = tid >> 4;
    int oo = tid & 63, kk2 = tid >> 6;

    for (int kc = 0; kc < FINv; kc += 16) {
        __syncthreads();
        {
            int f = kc + kk;
            float xv = x[b * FINv + f];
            const float* Npf = Np + f;
            const float* ef = e + (size_t)b * Nn * FINv + f;
            #pragma unroll
            for (int i = 0; i < 8; i++) {
                int n = nb + i * 8;
                int ng = n0 + n;
                aT[kk][n] = xv * Npf[ng * FINv] * ef[(size_t)ng * FINv];
            }
            #pragma unroll
            for (int i = 0; i < 8; i++) {
                int k = kk2 + i * 2;
                bs[k][oo] = wg[(kc + k) * FOv + oo];
            }
        }
        __syncthreads();
        #pragma unroll
        for (int k = 0; k < 16; k++) {
            float4 a0 = *(float4*)&aT[k][tn * 8];
            float4 a1 = *(float4*)&aT[k][tn * 8 + 4];
            float4 bv = *(float4*)&bs[k][to * 4];
            float av[8] = {a0.x, a0.y, a0.z, a0.w, a1.x, a1.y, a1.z, a1.w};
            float bw[4] = {bv.x, bv.y, bv.z, bv.w};
            #pragma unroll
            for (int i = 0; i < 8; i++)
                #pragma unroll
                for (int j = 0; j < 4; j++)
                    acc[i][j] += av[i] * bw[j];
        }
    }
    float* dst = g_h + (((size_t)(b * Hh + h)) * Nn + n0) * FOv;
    #pragma unroll
    for (int i = 0; i < 8; i++) {
        int n = tn * 8 + i;
        float4 v = make_float4(acc[i][0], acc[i][1], acc[i][2], acc[i][3]);
        *(float4*)&dst[(size_t)n * FOv + to * 4] = v;
    }
}

// ---------------- K2: s,d attention terms ----------------
__global__ void k_sd(const float* __restrict__ a_src, const float* __restrict__ a_dst) {
    int gw = (blockIdx.x * blockDim.x + threadIdx.x) >> 5;
    int lane = threadIdx.x & 31;
    int h = (gw >> 10) & 7;
    const float* hp = g_h + (size_t)gw * FOv;
    float v0 = hp[lane], v1 = hp[lane + 32];
    float s = v0 * a_src[h * FOv + lane] + v1 * a_src[h * FOv + lane + 32];
    float d = v0 * a_dst[h * FOv + lane] + v1 * a_dst[h * FOv + lane + 32];
    #pragma unroll
    for (int off = 16; off; off >>= 1) {
        s += __shfl_down_sync(0xffffffffu, s, off);
        d += __shfl_down_sync(0xffffffffu, d, off);
    }
    if (lane == 0) { g_s[gw] = s; g_d[gw] = d; }
}

// ---------------- helpers ----------------
static __device__ __forceinline__ uint32_t to_tf32(float f) {
    uint32_t u;
    asm("cvt.rna.tf32.f32 %0, %1;" : "=r"(u) : "f"(f));
    return u;
}
static __device__ __forceinline__ void mma_tf32(float* c, const uint32_t* a, uint32_t b0, uint32_t b1) {
    asm volatile(
        "mma.sync.aligned.m16n8k8.row.col.f32.tf32.tf32.f32 "
        "{%0,%1,%2,%3}, {%4,%5,%6,%7}, {%8,%9}, {%0,%1,%2,%3};"
        : "+f"(c[0]), "+f"(c[1]), "+f"(c[2]), "+f"(c[3])
        : "r"(a[0]), "r"(a[1]), "r"(a[2]), "r"(a[3]), "r"(b0), "r"(b1));
}

// ---------------- K3: fused masked softmax + mma.sync tf32 aggregation ----------------
// CTA per (b,h,128-row tile); 4 warps, each warp owns 32 rows x 64 cols of C.
// mma m16n8k8: m=graph row n, n=output feature o, k=neighbor m.
__global__ __launch_bounds__(128) void k_attn() {
    __shared__ uint32_t hs[32][68];   // h chunk, tf32 bits  [k=m][o]
    __shared__ float ds[Nn];          // d vector
    int tid = threadIdx.x;
    int w = tid >> 5, lane = tid & 31;
    int gr = lane >> 2, lc = lane & 3;
    int nt = blockIdx.x, h = blockIdx.y, b = blockIdx.z;
    int bh = b * Hh + h;
    int n0 = nt * 128;

    {   // preload d (1024 floats)
        const float4* dsrc = (const float4*)(g_d + bh * Nn);
        float4* d4 = (float4*)ds;
        d4[tid] = dsrc[tid];
        d4[tid + 128] = dsrc[tid + 128];
    }
    // this lane's 4 rows: base + {0,8,16,24}
    int rbase = n0 + w * 32 + gr;
    float sv[4];
    const unsigned* bb[4];
    #pragma unroll
    for (int i = 0; i < 4; i++) {
        sv[i] = g_s[bh * Nn + rbase + i * 8];
        bb[i] = g_abits + (size_t)(b * Nn + rbase + i * 8) * 32;
    }
    const float* hbase = g_h + (size_t)bh * Nn * FOv;

    float c[2][8][4];
    #pragma unroll
    for (int s2 = 0; s2 < 2; s2++)
        #pragma unroll
        for (int ot = 0; ot < 8; ot++)
            #pragma unroll
            for (int r = 0; r < 4; r++) c[s2][ot][r] = 0.f;
    float rs[4] = {0.f, 0.f, 0.f, 0.f};

    for (int ch = 0; ch < 32; ch++) {
        int m0 = ch * 32;
        __syncthreads();
        // stage h chunk (32 x 64), cvt to tf32 at store
        #pragma unroll
        for (int i = 0; i < 4; i++) {
            int idx = i * 128 + tid;
            int m = idx >> 4, o4 = idx & 15;
            float4 v = *(const float4*)&hbase[(size_t)(m0 + m) * FOv + o4 * 4];
            uint4 u;
            u.x = to_tf32(v.x); u.y = to_tf32(v.y);
            u.z = to_tf32(v.z); u.w = to_tf32(v.w);
            *(uint4*)&hs[m][o4 * 4] = u;
        }
        __syncthreads();
        unsigned bw0 = bb[0][ch], bw1 = bb[1][ch], bw2 = bb[2][ch], bw3 = bb[3][ch];
        unsigned bwv[4] = {bw0, bw1, bw2, bw3};
        #pragma unroll
        for (int j = 0; j < 4; j++) {
            float d0 = ds[m0 + j * 8 + lc];
            float d1 = ds[m0 + j * 8 + lc + 4];
            int cc0 = j * 8 + lc, cc1 = cc0 + 4;
            uint32_t afr[2][4];
            #pragma unroll
            for (int sub = 0; sub < 2; sub++) {
                #pragma unroll
                for (int rr = 0; rr < 2; rr++) {
                    int ri = sub * 2 + rr;
                    float t0 = sv[ri] + d0;
                    float l0 = fmaxf(t0, 0.2f * t0);
                    float e0 = __expf(l0);
                    e0 = ((bwv[ri] >> cc0) & 1u) ? e0 : 0.f;
                    float t1 = sv[ri] + d1;
                    float l1 = fmaxf(t1, 0.2f * t1);
                    float e1 = __expf(l1);
                    e1 = ((bwv[ri] >> cc1) & 1u) ? e1 : 0.f;
                    rs[ri] += e0 + e1;
                    afr[sub][rr]     = to_tf32(e0);   // (row, cc0)
                    afr[sub][rr + 2] = to_tf32(e1);   // (row, cc1)
                }
            }
            #pragma unroll
            for (int ot = 0; ot < 8; ot++) {
                uint32_t b0 = hs[j * 8 + lc][ot * 8 + gr];
                uint32_t b1 = hs[j * 8 + lc + 4][ot * 8 + gr];
                mma_tf32(c[0][ot], afr[0], b0, b1);
                mma_tf32(c[1][ot], afr[1], b0, b1);
            }
        }
    }
    // reduce rowsums across the 4 lanes of each quad
    #pragma unroll
    for (int i = 0; i < 4; i++) {
        rs[i] += __shfl_xor_sync(0xffffffffu, rs[i], 1);
        rs[i] += __shfl_xor_sync(0xffffffffu, rs[i], 2);
    }
    float inv[4];
    #pragma unroll
    for (int i = 0; i < 4; i++) inv[i] = 1.f / rs[i];

    float* ob = g_hout + (size_t)bh * Nn * FOv;
    #pragma unroll
    for (int sub = 0; sub < 2; sub++) {
        #pragma unroll
        for (int ot = 0; ot < 8; ot++) {
            int row = rbase + sub * 16;           // = n0 + w*32 + sub*16 + gr
            int o = ot * 8 + lc * 2;
            float2 lo = make_float2(c[sub][ot][0] * inv[sub * 2],
                                    c[sub][ot][1] * inv[sub * 2]);
            float2 hi = make_float2(c[sub][ot][2] * inv[sub * 2 + 1],
                                    c[sub][ot][3] * inv[sub * 2 + 1]);
            *(float2*)&ob[(size_t)row * FOv + o] = lo;
            *(float2*)&ob[(size_t)(row + 8) * FOv + o] = hi;
        }
    }
}

// ---------------- K4: head mean + bias + node mask ----------------
__global__ void k_final(const float* __restrict__ mask, const float* __restrict__ bias,
                        float* __restrict__ out) {
    int idx = blockIdx.x * blockDim.x + threadIdx.x;
    int o4 = idx & 15;
    int n = (idx >> 4) & (Nn - 1);
    int b = idx >> 14;
    float4 acc = make_float4(0.f, 0.f, 0.f, 0.f);
    #pragma unroll
    for (int h = 0; h < Hh; h++) {
        const float4 v = *(const float4*)&g_hout[(((size_t)(b * Hh + h)) * Nn + n) * FOv + o4 * 4];
        acc.x += v.x; acc.y += v.y; acc.z += v.z; acc.w += v.w;
    }
    float mz = mask[b * Nn + n];
    float m8 = mz * 0.125f;
    float4 bv = *(const float4*)&bias[o4 * 4];
    float4 r;
    r.x = fmaf(acc.x, m8, mz * bv.x);
    r.y = fmaf(acc.y, m8, mz * bv.y);
    r.z = fmaf(acc.z, m8, mz * bv.z);
    r.w = fmaf(acc.w, m8, mz * bv.w);
    ((float4*)out)[idx] = r;
}

// ---------------- launch ----------------
extern "C" void kernel_launch(void* const* d_in, const int* in_sizes, int n_in,
                              void* d_out, int out_size) {
    const float* x     = (const float*)d_in[0];
    const int*   A     = (const int*)  d_in[1];
    const float* mask  = (const float*)d_in[2];
    const float* e     = (const float*)d_in[4];
    const float* Np    = (const float*)d_in[5];
    const float* w     = (const float*)d_in[6];
    const float* a_src = (const float*)d_in[7];
    const float* a_dst = (const float*)d_in[8];
    const float* bias  = (const float*)d_in[9];
    float* out = (float*)d_out;

    k_pack <<<1024, 256>>>(A);
    k_feat <<<dim3(16, Hh, Bsz), 128>>>(x, e, Np, w);
    k_sd   <<<8192, 256>>>(a_src, a_dst);
    k_attn <<<dim3(8, Hh, Bsz), 128>>>();
    k_final<<<512, 256>>>(mask, bias, out);
}

// round 4
// speedup vs baseline: 2.4431x; 1.3748x over previous
#include <cuda_runtime.h>
#include <cstdint>

#define Bsz 8
#define Nn 1024
#define Hh 8
#define FOv 64
#define FINv 256
#define LOG2E 1.4426950408889634f

// ---------------- device scratch ----------------
__device__ unsigned g_abits[Bsz * Nn * 32];                 // packed adjacency
__device__ float g_h[(size_t)Bsz * Hh * Nn * FOv];          // h[b][h][n][o]
__device__ float g_s[Bsz * Hh * Nn];                        // pre-scaled by log2e
__device__ float g_d[Bsz * Hh * Nn];                        // pre-scaled by log2e
__device__ float g_hout[(size_t)Bsz * Hh * Nn * FOv];

// ---------------- helpers ----------------
static __device__ __forceinline__ uint32_t to_tf32(float f) {
    uint32_t u;
    asm("cvt.rna.tf32.f32 %0, %1;" : "=r"(u) : "f"(f));
    return u;
}
static __device__ __forceinline__ float ex2f(float x) {
    float y;
    asm("ex2.approx.f32 %0, %1;" : "=f"(y) : "f"(x));
    return y;
}
static __device__ __forceinline__ void mma_tf32(float* c, const uint32_t* a, uint32_t b0, uint32_t b1) {
    asm volatile(
        "mma.sync.aligned.m16n8k8.row.col.f32.tf32.tf32.f32 "
        "{%0,%1,%2,%3}, {%4,%5,%6,%7}, {%8,%9}, {%0,%1,%2,%3};"
        : "+f"(c[0]), "+f"(c[1]), "+f"(c[2]), "+f"(c[3])
        : "r"(a[0]), "r"(a[1]), "r"(a[2]), "r"(a[3]), "r"(b0), "r"(b1));
}

// ---------------- K0: pack adjacency ----------------
__global__ void k_pack(const int* __restrict__ A) {
    int warp = (blockIdx.x * blockDim.x + threadIdx.x) >> 5;
    int lane = threadIdx.x & 31;
    const int* row = A + (size_t)warp * Nn;
    unsigned* dst = g_abits + warp * 32;
    #pragma unroll
    for (int w = 0; w < 32; w++) {
        unsigned bits = __ballot_sync(0xffffffffu, row[w * 32 + lane] > 0);
        if (lane == 0) dst[w] = bits;
    }
}

// ---------------- K1: feature GEMM (all heads) + fused s,d ----------------
// CTA per (64-row tile, b). recx staged once in tf32; loop 4 head-pair iterations.
// 8 warps: warp = (head parity hp = w>>2, row block wr = (w&3)*16).
#define RECX_STRIDE 260
#define W_STRIDE 72
#define OFF_W    66560                       // recx: 64*260*4
#define OFF_ASD  (66560 + 147456)            // W: 2*256*72*4
#define FEAT_SMEM (OFF_ASD + 4096)           // asd: 1024 floats

__global__ __launch_bounds__(256) void k_feat(
    const float* __restrict__ x, const float* __restrict__ e,
    const float* __restrict__ Np, const float* __restrict__ wg,
    const float* __restrict__ a_src, const float* __restrict__ a_dst)
{
    extern __shared__ unsigned char sm_[];
    uint32_t* recx_s = (uint32_t*)sm_;
    uint32_t* W_s = (uint32_t*)(sm_ + OFF_W);
    float* asd_s = (float*)(sm_ + OFF_ASD);
    int nt = blockIdx.x, b = blockIdx.y;
    int n0 = nt * 64;
    int tid = threadIdx.x;
    int wp = tid >> 5, lane = tid & 31;
    int gr = lane >> 2, lc = lane & 3;
    int hp = wp >> 2;              // head parity
    int wr = (wp & 3) * 16;        // row base in tile

    // stage a_src/a_dst (512 floats each)
    asd_s[tid] = a_src[tid];
    asd_s[tid + 256] = a_src[tid + 256];
    asd_s[512 + tid] = a_dst[tid];
    asd_s[768 + tid] = a_dst[tid + 256];

    // stage recx: row = tid>>2, f-quarter = (tid&3)*64
    {
        int rr = tid >> 2;
        int f0 = (tid & 3) * 64;
        const float* xrow = x + b * FINv;
        const float* np = Np + (size_t)(n0 + rr) * FINv;
        const float* ee = e + ((size_t)b * Nn + n0 + rr) * FINv;
        uint32_t* dstr = recx_s + rr * RECX_STRIDE + f0;
        #pragma unroll
        for (int i = 0; i < 16; i++) {
            float4 xv = *(const float4*)&xrow[f0 + i * 4];
            float4 nv = *(const float4*)&np[f0 + i * 4];
            float4 ev = *(const float4*)&ee[f0 + i * 4];
            dstr[i * 4 + 0] = to_tf32(xv.x * nv.x * ev.x);
            dstr[i * 4 + 1] = to_tf32(xv.y * nv.y * ev.y);
            dstr[i * 4 + 2] = to_tf32(xv.z * nv.z * ev.z);
            dstr[i * 4 + 3] = to_tf32(xv.w * nv.w * ev.w);
        }
    }

    for (int it = 0; it < 4; it++) {
        __syncthreads();   // recx ready (it=0) / prior mma reads done
        // stage W for heads it*2, it*2+1
        {
            const float* wsrc = wg + (size_t)(it * 2) * FINv * FOv;
            #pragma unroll
            for (int i = 0; i < 32; i++) {
                int idx = i * 256 + tid;       // float4 index 0..8191
                int hh = idx >> 12;
                int r = idx & 4095;
                int f = r >> 4, o4 = r & 15;
                float4 v = *(const float4*)&wsrc[(size_t)hh * FINv * FOv + f * FOv + o4 * 4];
                uint32_t* dd = W_s + hh * (256 * W_STRIDE) + f * W_STRIDE + o4 * 4;
                dd[0] = to_tf32(v.x); dd[1] = to_tf32(v.y);
                dd[2] = to_tf32(v.z); dd[3] = to_tf32(v.w);
            }
        }
        __syncthreads();
        int h = it * 2 + hp;
        const uint32_t* Wh = W_s + hp * (256 * W_STRIDE);
        float c[8][4];
        #pragma unroll
        for (int ot = 0; ot < 8; ot++)
            #pragma unroll
            for (int r = 0; r < 4; r++) c[ot][r] = 0.f;
        #pragma unroll
        for (int ks = 0; ks < 32; ks++) {
            uint32_t a[4];
            const uint32_t* ar0 = recx_s + (wr + gr) * RECX_STRIDE + ks * 8;
            const uint32_t* ar1 = ar0 + 8 * RECX_STRIDE;
            a[0] = ar0[lc]; a[1] = ar1[lc]; a[2] = ar0[lc + 4]; a[3] = ar1[lc + 4];
            const uint32_t* br0 = Wh + (ks * 8 + lc) * W_STRIDE + gr;
            const uint32_t* br1 = br0 + 4 * W_STRIDE;
            #pragma unroll
            for (int ot = 0; ot < 8; ot++)
                mma_tf32(c[ot], a, br0[ot * 8], br1[ot * 8]);
        }
        // epilogue: store h, fused s,d
        int bh = b * Hh + h;
        float* dsth = g_h + ((size_t)bh * Nn + n0 + wr) * FOv;
        const float* as = asd_s + h * 64;
        const float* ad = asd_s + 512 + h * 64;
        float s0 = 0.f, s1 = 0.f, d0 = 0.f, d1 = 0.f;
        #pragma unroll
        for (int ot = 0; ot < 8; ot++) {
            int o = ot * 8 + lc * 2;
            *(float2*)&dsth[(size_t)gr * FOv + o] = make_float2(c[ot][0], c[ot][1]);
            *(float2*)&dsth[(size_t)(gr + 8) * FOv + o] = make_float2(c[ot][2], c[ot][3]);
            float a0 = as[o], a1 = as[o + 1];
            float b0 = ad[o], b1 = ad[o + 1];
            s0 += c[ot][0] * a0 + c[ot][1] * a1;
            s1 += c[ot][2] * a0 + c[ot][3] * a1;
            d0 += c[ot][0] * b0 + c[ot][1] * b1;
            d1 += c[ot][2] * b0 + c[ot][3] * b1;
        }
        #pragma unroll
        for (int off = 1; off <= 2; off <<= 1) {
            s0 += __shfl_xor_sync(0xffffffffu, s0, off);
            s1 += __shfl_xor_sync(0xffffffffu, s1, off);
            d0 += __shfl_xor_sync(0xffffffffu, d0, off);
            d1 += __shfl_xor_sync(0xffffffffu, d1, off);
        }
        if (lc == 0) {
            int rb = bh * Nn + n0 + wr + gr;
            g_s[rb] = s0 * LOG2E; g_s[rb + 8] = s1 * LOG2E;
            g_d[rb] = d0 * LOG2E; g_d[rb + 8] = d1 * LOG2E;
        }
    }
}

// ---------------- K3: fused masked softmax + mma.sync tf32 aggregation ----------------
__global__ __launch_bounds__(128) void k_attn() {
    __shared__ uint32_t hs[32][68];   // h chunk, tf32 bits  [k=m][o]
    __shared__ float ds[Nn];          // d vector (pre-scaled by log2e)
    int tid = threadIdx.x;
    int w = tid >> 5, lane = tid & 31;
    int gr = lane >> 2, lc = lane & 3;
    int nt = blockIdx.x, h = blockIdx.y, b = blockIdx.z;
    int bh = b * Hh + h;
    int n0 = nt * 128;

    {
        const float4* dsrc = (const float4*)(g_d + bh * Nn);
        float4* d4 = (float4*)ds;
        d4[tid] = dsrc[tid];
        d4[tid + 128] = dsrc[tid + 128];
    }
    int rbase = n0 + w * 32 + gr;
    float sv[4];
    const unsigned* bb[4];
    #pragma unroll
    for (int i = 0; i < 4; i++) {
        sv[i] = g_s[bh * Nn + rbase + i * 8];
        bb[i] = g_abits + (size_t)(b * Nn + rbase + i * 8) * 32;
    }
    const float* hbase = g_h + (size_t)bh * Nn * FOv;

    float c[2][8][4];
    #pragma unroll
    for (int s2 = 0; s2 < 2; s2++)
        #pragma unroll
        for (int ot = 0; ot < 8; ot++)
            #pragma unroll
            for (int r = 0; r < 4; r++) c[s2][ot][r] = 0.f;
    float rs[4] = {0.f, 0.f, 0.f, 0.f};

    for (int ch = 0; ch < 32; ch++) {
        int m0 = ch * 32;
        __syncthreads();
        #pragma unroll
        for (int i = 0; i < 4; i++) {
            int idx = i * 128 + tid;
            int m = idx >> 4, o4 = idx & 15;
            float4 v = *(const float4*)&hbase[(size_t)(m0 + m) * FOv + o4 * 4];
            uint4 u;
            u.x = to_tf32(v.x); u.y = to_tf32(v.y);
            u.z = to_tf32(v.z); u.w = to_tf32(v.w);
            *(uint4*)&hs[m][o4 * 4] = u;
        }
        __syncthreads();
        unsigned bwv[4] = {bb[0][ch], bb[1][ch], bb[2][ch], bb[3][ch]};
        #pragma unroll
        for (int j = 0; j < 4; j++) {
            float d0 = ds[m0 + j * 8 + lc];
            float d1 = ds[m0 + j * 8 + lc + 4];
            int cc0 = j * 8 + lc, cc1 = cc0 + 4;
            uint32_t afr[2][4];
            #pragma unroll
            for (int sub = 0; sub < 2; sub++) {
                #pragma unroll
                for (int rr = 0; rr < 2; rr++) {
                    int ri = sub * 2 + rr;
                    float t0 = sv[ri] + d0;
                    float l0 = fmaxf(t0, 0.2f * t0);
                    float e0 = ex2f(l0);
                    e0 = ((bwv[ri] >> cc0) & 1u) ? e0 : 0.f;
                    float t1 = sv[ri] + d1;
                    float l1 = fmaxf(t1, 0.2f * t1);
                    float e1 = ex2f(l1);
                    e1 = ((bwv[ri] >> cc1) & 1u) ? e1 : 0.f;
                    rs[ri] += e0 + e1;
                    afr[sub][rr]     = to_tf32(e0);
                    afr[sub][rr + 2] = to_tf32(e1);
                }
            }
            #pragma unroll
            for (int ot = 0; ot < 8; ot++) {
                uint32_t b0 = hs[j * 8 + lc][ot * 8 + gr];
                uint32_t b1 = hs[j * 8 + lc + 4][ot * 8 + gr];
                mma_tf32(c[0][ot], afr[0], b0, b1);
                mma_tf32(c[1][ot], afr[1], b0, b1);
            }
        }
    }
    #pragma unroll
    for (int i = 0; i < 4; i++) {
        rs[i] += __shfl_xor_sync(0xffffffffu, rs[i], 1);
        rs[i] += __shfl_xor_sync(0xffffffffu, rs[i], 2);
    }
    float inv[4];
    #pragma unroll
    for (int i = 0; i < 4; i++) inv[i] = 1.f / rs[i];

    float* ob = g_hout + (size_t)bh * Nn * FOv;
    #pragma unroll
    for (int sub = 0; sub < 2; sub++) {
        #pragma unroll
        for (int ot = 0; ot < 8; ot++) {
            int row = rbase + sub * 16;
            int o = ot * 8 + lc * 2;
            float2 lo = make_float2(c[sub][ot][0] * inv[sub * 2],
                                    c[sub][ot][1] * inv[sub * 2]);
            float2 hi = make_float2(c[sub][ot][2] * inv[sub * 2 + 1],
                                    c[sub][ot][3] * inv[sub * 2 + 1]);
            *(float2*)&ob[(size_t)row * FOv + o] = lo;
            *(float2*)&ob[(size_t)(row + 8) * FOv + o] = hi;
        }
    }
}

// ---------------- K4: head mean + bias + node mask ----------------
__global__ void k_final(const float* __restrict__ mask, const float* __restrict__ bias,
                        float* __restrict__ out) {
    int idx = blockIdx.x * blockDim.x + threadIdx.x;
    int o4 = idx & 15;
    int n = (idx >> 4) & (Nn - 1);
    int b = idx >> 14;
    float4 acc = make_float4(0.f, 0.f, 0.f, 0.f);
    #pragma unroll
    for (int h = 0; h < Hh; h++) {
        const float4 v = *(const float4*)&g_hout[(((size_t)(b * Hh + h)) * Nn + n) * FOv + o4 * 4];
        acc.x += v.x; acc.y += v.y; acc.z += v.z; acc.w += v.w;
    }
    float mz = mask[b * Nn + n];
    float m8 = mz * 0.125f;
    float4 bv = *(const float4*)&bias[o4 * 4];
    float4 r;
    r.x = fmaf(acc.x, m8, mz * bv.x);
    r.y = fmaf(acc.y, m8, mz * bv.y);
    r.z = fmaf(acc.z, m8, mz * bv.z);
    r.w = fmaf(acc.w, m8, mz * bv.w);
    ((float4*)out)[idx] = r;
}

// ---------------- launch ----------------
extern "C" void kernel_launch(void* const* d_in, const int* in_sizes, int n_in,
                              void* d_out, int out_size) {
    const float* x     = (const float*)d_in[0];
    const int*   A     = (const int*)  d_in[1];
    const float* mask  = (const float*)d_in[2];
    const float* e     = (const float*)d_in[4];
    const float* Np    = (const float*)d_in[5];
    const float* w     = (const float*)d_in[6];
    const float* a_src = (const float*)d_in[7];
    const float* a_dst = (const float*)d_in[8];
    const float* bias  = (const float*)d_in[9];
    float* out = (float*)d_out;

    cudaFuncSetAttribute((const void*)k_feat,
                         cudaFuncAttributeMaxDynamicSharedMemorySize, FEAT_SMEM);

    k_pack <<<1024, 256>>>(A);
    k_feat <<<dim3(16, Bsz), 256, FEAT_SMEM>>>(x, e, Np, w, a_src, a_dst);
    k_attn <<<dim3(8, Hh, Bsz), 128>>>();
    k_final<<<512, 256>>>(mask, bias, out);
}